// round 7
// baseline (speedup 1.0000x reference)
#include <cuda_runtime.h>
#include <math.h>

typedef unsigned long long u64;

#define TILE 16
// smem float offsets (same data layout as R6)
#define SM_SX     0        // 64*400
#define SM_SPN    25600    // 2*400
#define SM_XCP    26400    // 12 slots * 400 px * 2 (pair {A,B})
#define SM_D3AP   36000    // 4 cpl * 324 * 2 (pair {h0,h1})
#define SM_DW1P   38592    // 64*27*2
#define SM_DW3AP  42048    // 64*27*2
#define SM_DW3BP  45504    // 64*9*2
#define SM_WOUTT  46656    // [cp][o] 64*64
#define SM_BDW1P  50752    // 64*2
#define SM_BDW3AP 50880
#define SM_BDW3BP 51008
#define SM_BOUT   51136    // 64
#define SM_WPN    51200    // 256
#define SM_BPN    51456    // 128
#define SM_BIN    51584    // 256
#define SM_TOTAL  51840    // 207360 bytes

// w_in transposed+paired: c_winT2[k*128 + c2] = {w_in[2c2][k], w_in[2c2+1][k]}
__constant__ u64 c_winT2[64 * 128];
__device__ u64 g_winT2[64 * 128];

__global__ void prep_winT(const float* __restrict__ w_in) {
    int i = blockIdx.x * 256 + threadIdx.x;   // 0..8191
    int k = i >> 7, c2 = i & 127;
    float lo = w_in[(2 * c2) * 64 + k];
    float hi = w_in[(2 * c2 + 1) * 64 + k];
    u64 r;
    asm("mov.b64 %0,{%1,%2};" : "=l"(r) : "f"(lo), "f"(hi));
    g_winT2[i] = r;
}

__device__ __forceinline__ u64 pk2(float lo, float hi) {
    u64 r; asm("mov.b64 %0,{%1,%2};" : "=l"(r) : "f"(lo), "f"(hi)); return r;
}
__device__ __forceinline__ void upk2(u64 v, float& lo, float& hi) {
    asm("mov.b64 {%0,%1},%2;" : "=f"(lo), "=f"(hi) : "l"(v));
}
__device__ __forceinline__ void fma2(u64& d, u64 a, u64 b) {
    asm("fma.rn.f32x2 %0,%1,%2,%0;" : "+l"(d) : "l"(a), "l"(b));
}
__device__ __forceinline__ u64 lds64(const float* p) { return *(const u64*)p; }

__device__ __forceinline__ float gelu_exact(float v) {
    return 0.5f * v * (1.0f + erff(v * 0.70710678118654752f));
}

// Phase A for ONE halo pixel q. NPAIRS = # of A-side xi pairs {0,2,6}.
template<int NPAIRS>
__device__ __forceinline__ void phaseA(float* sm, int g, int q, float m,
                                       float pnA, float pnB)
{
    const int bBase = 64 + 12 * g;                  // B-side xi base (even)
    const int bIdx  = 32 + 6 * g;                   // pair index (even)
    const int aBase = (NPAIRS == 2) ? 0 : (12 * g - 128);
    const int aIdx  = aBase >> 1;
    u64 aB[6];
    u64 aA[NPAIRS > 0 ? NPAIRS : 1];
#pragma unroll
    for (int j = 0; j < 6; ++j) aB[j] = lds64(sm + SM_BIN + bBase + 2 * j);
#pragma unroll
    for (int j = 0; j < NPAIRS; ++j) aA[j] = lds64(sm + SM_BIN + aBase + 2 * j);

#pragma unroll 4
    for (int k = 0; k < 64; ++k) {
        float s0 = sm[SM_SX + k * 400 + q];
        u64 sp = pk2(s0, s0);
        const ulonglong2* wB = (const ulonglong2*)(c_winT2 + k * 128 + bIdx);
        ulonglong2 w01 = wB[0], w23 = wB[1], w45 = wB[2];
        fma2(aB[0], w01.x, sp); fma2(aB[1], w01.y, sp);
        fma2(aB[2], w23.x, sp); fma2(aB[3], w23.y, sp);
        fma2(aB[4], w45.x, sp); fma2(aB[5], w45.y, sp);
        if (NPAIRS == 2) {
            const ulonglong2* wA = (const ulonglong2*)(c_winT2 + k * 128 + aIdx);
            ulonglong2 a01 = wA[0];
            fma2(aA[0], a01.x, sp); fma2(aA[1], a01.y, sp);
        } else if (NPAIRS == 6) {
            const ulonglong2* wA = (const ulonglong2*)(c_winT2 + k * 128 + aIdx);
            ulonglong2 a01 = wA[0], a23 = wA[1], a45 = wA[2];
            fma2(aA[0], a01.x, sp); fma2(aA[1], a01.y, sp);
            fma2(aA[2], a23.x, sp); fma2(aA[3], a23.y, sp);
            fma2(aA[4], a45.x, sp); fma2(aA[5], a45.y, sp);
        }
    }

    float A0[12], B0[12];
#pragma unroll
    for (int j = 0; j < 6; ++j) upk2(aB[j], B0[2 * j], B0[2 * j + 1]);
    if (NPAIRS == 6) {
#pragma unroll
        for (int j = 0; j < 6; ++j) upk2(aA[j], A0[2 * j], A0[2 * j + 1]);
    } else if (NPAIRS == 2) {
        upk2(aA[0], A0[8], A0[9]);
        upk2(aA[1], A0[10], A0[11]);
    }
#pragma unroll
    for (int s = 0; s < 12; ++s) {
        const bool isPN = (NPAIRS == 0) || (NPAIRS == 2 && s < 8);
        if (isPN) {
            int c = 12 * g + s;
            float w0 = sm[SM_WPN + 2 * c], w1 = sm[SM_WPN + 2 * c + 1];
            float bb = sm[SM_BPN + c];
            A0[s] = fmaf(w0, pnA, fmaf(w1, pnB, bb));
        }
        float2 v; v.x = A0[s] * m; v.y = B0[s] * m;
        *(float2*)&sm[SM_XCP + (s * 400 + q) * 2] = v;
    }
}

__global__ void __launch_bounds__(512, 1)
ffn_fused_kernel(const float* __restrict__ x,
                 const float* __restrict__ pneff,
                 const float* __restrict__ w_pn,  const float* __restrict__ b_pn,
                 const float* __restrict__ w_dw1, const float* __restrict__ b_dw1,
                 const float* __restrict__ w_dw3a,const float* __restrict__ b_dw3a,
                 const float* __restrict__ w_dw3b,const float* __restrict__ b_dw3b,
                 const float* __restrict__ w_out, const float* __restrict__ b_out,
                 const float* __restrict__ b_in,
                 float* __restrict__ out)
{
    extern __shared__ float sm[];
    const int tid = threadIdx.x;
    const int bx0 = blockIdx.x * TILE;
    const int by0 = blockIdx.y * TILE;
    const int b   = blockIdx.z;

    // ---- stage paired weights/biases ----
    for (int v = tid; v < 1728; v += 512) {
        int cp = v / 27, t = v - cp * 27;
        sm[SM_DW1P + 2 * v]      = w_dw1[cp * 27 + t];
        sm[SM_DW1P + 2 * v + 1]  = w_dw1[(cp + 64) * 27 + t];
        sm[SM_DW3AP + 2 * v]     = w_dw3a[cp * 27 + t];
        sm[SM_DW3AP + 2 * v + 1] = w_dw3a[(cp + 64) * 27 + t];
    }
    for (int v = tid; v < 576; v += 512) {
        int cp = v / 9, t = v - cp * 9;
        sm[SM_DW3BP + 2 * v]     = w_dw3b[cp * 9 + t];
        sm[SM_DW3BP + 2 * v + 1] = w_dw3b[(cp + 64) * 9 + t];
    }
    for (int v = tid; v < 4096; v += 512) {
        int o = v >> 6, cp = v & 63;
        sm[SM_WOUTT + cp * 64 + o] = w_out[v];
    }
    if (tid < 64) {
        sm[SM_BDW1P + 2 * tid]      = b_dw1[tid];
        sm[SM_BDW1P + 2 * tid + 1]  = b_dw1[tid + 64];
        sm[SM_BDW3AP + 2 * tid]     = b_dw3a[tid];
        sm[SM_BDW3AP + 2 * tid + 1] = b_dw3a[tid + 64];
        sm[SM_BDW3BP + 2 * tid]     = b_dw3b[tid];
        sm[SM_BDW3BP + 2 * tid + 1] = b_dw3b[tid + 64];
        sm[SM_BOUT + tid] = b_out[tid];
    }
    if (tid < 256) { sm[SM_WPN + tid] = w_pn[tid]; sm[SM_BIN + tid] = b_in[tid]; }
    if (tid < 128) sm[SM_BPN + tid] = b_pn[tid];

    // ---- stage x tile + pn tile ----
    {
        const float* xb = x + (size_t)b * 64 * 65536;
        for (int c = 0; c < 64; ++c) {
            const float* xcp = xb + (size_t)c * 65536;
            for (int p = tid; p < 400; p += 512) {
                int ry = p / 20, rx = p - ry * 20;
                int gy = by0 + ry - 2, gx = bx0 + rx - 2;
                float vv = 0.0f;
                if ((unsigned)gy < 256u && (unsigned)gx < 256u) vv = xcp[gy * 256 + gx];
                sm[SM_SX + c * 400 + p] = vv;
            }
        }
        const float* pnb = pneff + (size_t)b * 2 * 65536;
        for (int c = 0; c < 2; ++c) {
            const float* pcp = pnb + (size_t)c * 65536;
            for (int p = tid; p < 400; p += 512) {
                int ry = p / 20, rx = p - ry * 20;
                int gy = by0 + ry - 2, gx = bx0 + rx - 2;
                float vv = 0.0f;
                if ((unsigned)gy < 256u && (unsigned)gx < 256u) vv = pcp[gy * 256 + gx];
                sm[SM_SPN + c * 400 + p] = vv;
            }
        }
    }
    __syncthreads();

    const bool doA = (tid < 400);
    const int q = doA ? tid : 0;
    float m = 0.0f, pnA = 0.0f, pnB = 0.0f;
    if (doA) {
        int ry = q / 20, rx = q - ry * 20;
        m = ((unsigned)(by0 + ry - 2) < 256u && (unsigned)(bx0 + rx - 2) < 256u) ? 1.f : 0.f;
        pnA = sm[SM_SPN + q];
        pnB = sm[SM_SPN + 400 + q];
    }

    const int px   = tid & 255;          // output pixel
    const int gh   = tid >> 8;           // 0: B1/o0-31, 1: B3/o32-63
    const int ty   = px >> 4;
    const int tx   = px & 15;
    const int warp = tid >> 5;
    const int lane = tid & 31;

    u64 acc[16];
#pragma unroll
    for (int mm = 0; mm < 16; ++mm) acc[mm] = 0ULL;

    for (int g = 0; g < 16; ++g) {
        // ---- Phase A (threads 0..399, one pixel each) ----
        if (doA) {
            if (g < 10)       phaseA<0>(sm, g, q, m, pnA, pnB);
            else if (g == 10) phaseA<2>(sm, g, q, m, pnA, pnB);
            else              phaseA<6>(sm, g, q, m, pnA, pnB);
        }
        __syncthreads();   // XCP ready

        // ---- B2: 16 warps, warp = (cpl, quarter) ----
        {
            const int cpl = warp >> 2, qtr = warp & 3;
            const int cp = 4 * g + cpl;
            u64 bias = lds64(sm + SM_BDW3AP + 2 * cp);
            const float* wp = sm + SM_DW3AP + cp * 54;
            const float* xb = sm + SM_XCP + (3 * cpl * 400) * 2;
            float* dst = sm + SM_D3AP + cpl * 648;
            for (int i = 81 * qtr + lane; i < 81 * qtr + 81; i += 32) {
                int qy = i / 18, qx = i - qy * 18;
                int gy = by0 + qy - 1, gx = bx0 + qx - 1;
                u64 d = bias;
#pragma unroll
                for (int j = 0; j < 3; ++j)
#pragma unroll
                    for (int ky = 0; ky < 3; ++ky)
#pragma unroll
                        for (int kx = 0; kx < 3; ++kx) {
                            u64 w  = lds64(wp + 2 * (j * 9 + ky * 3 + kx));
                            u64 xv = lds64(xb + (j * 400 + (qy + ky) * 20 + qx + kx) * 2);
                            fma2(d, w, xv);
                        }
                float da, db; upk2(d, da, db);
                bool ok = ((unsigned)gy < 256u) && ((unsigned)gx < 256u);
                float2 v; v.x = ok ? da : 0.f; v.y = ok ? db : 0.f;
                *(float2*)&dst[2 * i] = v;
            }
        }
        __syncthreads();   // D3A ready

        if (gh == 0) {
            // ---- B1 + proj (o 0..31) ----
#pragma unroll
            for (int cpl = 0; cpl < 4; ++cpl) {
                const int cp = 4 * g + cpl;
                u64 d1 = lds64(sm + SM_BDW1P + 2 * cp);
                const float* wp = sm + SM_DW1P + cp * 54;
                const float* xb = sm + SM_XCP + (3 * cpl * 400) * 2;
#pragma unroll
                for (int j = 0; j < 3; ++j)
#pragma unroll
                    for (int ky = 0; ky < 3; ++ky)
#pragma unroll
                        for (int kx = 0; kx < 3; ++kx) {
                            u64 w  = lds64(wp + 2 * (j * 9 + ky * 3 + kx));
                            u64 xv = lds64(xb + (j * 400 + (ty + 1 + ky) * 20 + tx + 1 + kx) * 2);
                            fma2(d1, w, xv);
                        }
                float d1a, d1b; upk2(d1, d1a, d1b);
                float g1 = gelu_exact(d1a) * d1b;
                u64 g1p = pk2(g1, g1);
                const ulonglong2* wo = (const ulonglong2*)(sm + SM_WOUTT + cp * 64);
#pragma unroll
                for (int mm = 0; mm < 8; ++mm) {
                    ulonglong2 w2 = wo[mm];
                    fma2(acc[2 * mm], w2.x, g1p);
                    fma2(acc[2 * mm + 1], w2.y, g1p);
                }
            }
        } else {
            // ---- B3 + proj (o 32..63) ----
#pragma unroll
            for (int cpl = 0; cpl < 4; ++cpl) {
                const int cp = 4 * g + cpl;
                u64 d = lds64(sm + SM_BDW3BP + 2 * cp);
                const float* wp = sm + SM_DW3BP + cp * 18;
                const float* db3 = sm + SM_D3AP + cpl * 648;
#pragma unroll
                for (int ky = 0; ky < 3; ++ky)
#pragma unroll
                    for (int kx = 0; kx < 3; ++kx) {
                        u64 w  = lds64(wp + 2 * (ky * 3 + kx));
                        u64 xv = lds64(db3 + ((ty + ky) * 18 + tx + kx) * 2);
                        fma2(d, w, xv);
                    }
                float da, dbv; upk2(d, da, dbv);
                float g2 = gelu_exact(da) * dbv;
                u64 g2p = pk2(g2, g2);
                const ulonglong2* wo = (const ulonglong2*)(sm + SM_WOUTT + cp * 64 + 32);
#pragma unroll
                for (int mm = 0; mm < 8; ++mm) {
                    ulonglong2 w2 = wo[mm];
                    fma2(acc[2 * mm], w2.x, g2p);
                    fma2(acc[2 * mm + 1], w2.y, g2p);
                }
            }
        }
        __syncthreads();   // protect XCP/D3A for next group
    }

    // ---- write output: gh=0 -> o 0..31, gh=1 -> o 32..63 ----
    float* ob = out + (size_t)b * 64 * 65536 + (size_t)(by0 + ty) * 256 + (bx0 + tx);
    const int ob0 = gh * 32;
#pragma unroll
    for (int mm = 0; mm < 16; ++mm) {
        float o0, o1; upk2(acc[mm], o0, o1);
        ob[(size_t)(ob0 + 2 * mm) * 65536]     = o0 + sm[SM_BOUT + ob0 + 2 * mm];
        ob[(size_t)(ob0 + 2 * mm + 1) * 65536] = o1 + sm[SM_BOUT + ob0 + 2 * mm + 1];
    }
}

extern "C" void kernel_launch(void* const* d_in, const int* in_sizes, int n_in,
                              void* d_out, int out_size)
{
    (void)in_sizes; (void)n_in; (void)out_size;
    const float* x      = (const float*)d_in[0];
    const float* pneff  = (const float*)d_in[1];
    const float* w_in   = (const float*)d_in[2];
    float* out = (float*)d_out;

    prep_winT<<<32, 256>>>(w_in);
    void* p_winT = nullptr;
    cudaGetSymbolAddress(&p_winT, g_winT2);
    cudaMemcpyToSymbolAsync(c_winT2, p_winT, 64 * 128 * sizeof(u64), 0,
                            cudaMemcpyDeviceToDevice, 0);

    const size_t smem_bytes = SM_TOTAL * sizeof(float);
    cudaFuncSetAttribute(ffn_fused_kernel,
                         cudaFuncAttributeMaxDynamicSharedMemorySize,
                         (int)smem_bytes);
    dim3 grid(16, 16, 4);
    ffn_fused_kernel<<<grid, 512, smem_bytes>>>(
        x, pneff,
        (const float*)d_in[4],  (const float*)d_in[5],
        (const float*)d_in[6],  (const float*)d_in[7],
        (const float*)d_in[8],  (const float*)d_in[9],
        (const float*)d_in[10], (const float*)d_in[11],
        (const float*)d_in[12], (const float*)d_in[13],
        (const float*)d_in[3],
        out);
}

// round 8
// speedup vs baseline: 1.5130x; 1.5130x over previous
#include <cuda_runtime.h>
#include <math.h>

// Round 8: tile 16x8, 256 threads, ~103KB smem -> 2 blocks/SM.
// Scalar FFMA (R5 style). Per-group smem staging of all weights.

#define HALO   240     // 20 x 12
// smem float offsets
#define SM_SX     0        // 64*240 = 15360
#define SM_SPN    15360    // 2*240  = 480
#define SM_XC     15840    // 24*240 = 5760  (slots 0-11 A-half, 12-23 B-half)
#define SM_D3A    21600    // 4 cpl * 2 h * 180 = 1440
#define SM_WT     23040    // 64*24  = 1536
#define SM_GDW1   24576    // 4*2*27 = 216
#define SM_GDW3A  24792    // 8*27   = 216
#define SM_GDW3B  25008    // 4*2*9  = 72
#define SM_GWOUT  25080    // 4*64   = 256
#define SM_BDW1   25336    // 128
#define SM_BDW3A  25464    // 128
#define SM_BDW3B  25592    // 128
#define SM_BOUT   25720    // 64
#define SM_WPN    25784    // 256
#define SM_BPN    26040    // 128
#define SM_BIN    26168    // 256
#define SM_TOTAL  26424    // 105696 bytes

__device__ __forceinline__ float gelu_exact(float v) {
    return 0.5f * v * (1.0f + erff(v * 0.70710678118654752f));
}

// Phase A for one halo pixel q. NCH4 = number of float4 weight groups per k:
//   3: B-half only (g<10, A-half all pn)
//   4: B-half + 4 A-xi (g==10, xc ch 128..131 -> slots 8..11)
//   6: B-half + 12 A-xi (g>=11)
template<int NCH4>
__device__ __forceinline__ void phaseA(float* sm, int g, int q, float m,
                                       float pnA, float pnB)
{
    float a[4 * NCH4];
#pragma unroll
    for (int j = 0; j < 12; ++j) a[j] = sm[SM_BIN + 64 + 12 * g + j];
    if (NCH4 == 4) {
#pragma unroll
        for (int j = 0; j < 4; ++j) a[12 + j] = sm[SM_BIN + j];
    } else if (NCH4 == 6) {
#pragma unroll
        for (int j = 0; j < 12; ++j) a[12 + j] = sm[SM_BIN + 12 * g - 128 + j];
    }
#pragma unroll 4
    for (int k = 0; k < 64; ++k) {
        float s0 = sm[SM_SX + k * 240 + q];
        const float* wt = sm + SM_WT + k * 24;
#pragma unroll
        for (int j = 0; j < NCH4; ++j) {
            float4 w = *(const float4*)(wt + 4 * j);
            a[4 * j]     = fmaf(w.x, s0, a[4 * j]);
            a[4 * j + 1] = fmaf(w.y, s0, a[4 * j + 1]);
            a[4 * j + 2] = fmaf(w.z, s0, a[4 * j + 2]);
            a[4 * j + 3] = fmaf(w.w, s0, a[4 * j + 3]);
        }
    }
    // B-half -> XC slots 12..23
#pragma unroll
    for (int s = 0; s < 12; ++s)
        sm[SM_XC + (12 + s) * 240 + q] = a[s] * m;
    // A-half -> XC slots 0..11 (pn or xi)
#pragma unroll
    for (int s = 0; s < 12; ++s) {
        float val;
        const bool isPN = (NCH4 == 3) || (NCH4 == 4 && s < 8);
        if (isPN) {
            int c = 12 * g + s;
            float w0 = sm[SM_WPN + 2 * c], w1 = sm[SM_WPN + 2 * c + 1];
            val = fmaf(w0, pnA, fmaf(w1, pnB, sm[SM_BPN + c]));
        } else if (NCH4 == 4) {
            val = a[12 + s - 8];
        } else {
            val = a[12 + s];
        }
        sm[SM_XC + s * 240 + q] = val * m;
    }
}

__global__ void __launch_bounds__(256, 2)
ffn_fused_kernel(const float* __restrict__ x,
                 const float* __restrict__ pneff,
                 const float* __restrict__ w_in,  const float* __restrict__ b_in,
                 const float* __restrict__ w_pn,  const float* __restrict__ b_pn,
                 const float* __restrict__ w_dw1, const float* __restrict__ b_dw1,
                 const float* __restrict__ w_dw3a,const float* __restrict__ b_dw3a,
                 const float* __restrict__ w_dw3b,const float* __restrict__ b_dw3b,
                 const float* __restrict__ w_out, const float* __restrict__ b_out,
                 float* __restrict__ out)
{
    extern __shared__ float sm[];
    const int tid = threadIdx.x;
    const int bx0 = blockIdx.x * 16;
    const int by0 = blockIdx.y * 8;
    const int b   = blockIdx.z;

    // ---- stage static biases/small weights ----
    if (tid < 128) {
        sm[SM_BDW1 + tid]  = b_dw1[tid];
        sm[SM_BDW3A + tid] = b_dw3a[tid];
        sm[SM_BDW3B + tid] = b_dw3b[tid];
        sm[SM_BPN + tid]   = b_pn[tid];
    }
    if (tid < 64) sm[SM_BOUT + tid] = b_out[tid];
    sm[SM_WPN + tid] = w_pn[tid];
    sm[SM_BIN + tid] = b_in[tid];

    // ---- stage x tile (20x12 halo, 64 ch) + pn tile ----
    {
        const float* xb = x + (size_t)b * 64 * 65536;
        for (int v = tid; v < 64 * HALO; v += 256) {
            int c = v / HALO, p = v - c * HALO;
            int ry = p / 20, rx = p - ry * 20;
            int gy = by0 + ry - 2, gx = bx0 + rx - 2;
            float vv = 0.0f;
            if ((unsigned)gy < 256u && (unsigned)gx < 256u)
                vv = xb[(size_t)c * 65536 + gy * 256 + gx];
            sm[SM_SX + c * HALO + p] = vv;
        }
        const float* pnb = pneff + (size_t)b * 2 * 65536;
        for (int v = tid; v < 2 * HALO; v += 256) {
            int c = v / HALO, p = v - c * HALO;
            int ry = p / 20, rx = p - ry * 20;
            int gy = by0 + ry - 2, gx = bx0 + rx - 2;
            float vv = 0.0f;
            if ((unsigned)gy < 256u && (unsigned)gx < 256u)
                vv = pnb[(size_t)c * 65536 + gy * 256 + gx];
            sm[SM_SPN + c * HALO + p] = vv;
        }
    }
    __syncthreads();

    const bool doA = (tid < HALO);
    const int q = doA ? tid : 0;
    float m = 0.0f, pnA = 0.0f, pnB = 0.0f;
    if (doA) {
        int ry = q / 20, rx = q - ry * 20;
        m = ((unsigned)(by0 + ry - 2) < 256u && (unsigned)(bx0 + rx - 2) < 256u) ? 1.f : 0.f;
        pnA = sm[SM_SPN + q];
        pnB = sm[SM_SPN + HALO + q];
    }

    const int px   = tid & 127;      // output pixel within 16x8 tile
    const int gh   = tid >> 7;       // 0: B1 + o0..31 ; 1: B3 + o32..63
    const int tyl  = px >> 4;        // 0..7
    const int tx   = px & 15;
    const int warp = tid >> 5;       // 0..7
    const int lane = tid & 31;

    float acc[32];
#pragma unroll
    for (int i = 0; i < 32; ++i) acc[i] = 0.0f;

    for (int g = 0; g < 16; ++g) {
        // ---- stage per-group weights ----
        {
            // WT: [k][24] cols 0-11 = B-half xi (64+12g+j); cols 12-23 = A-xi
            const int nw = (g < 10) ? 768 : (g == 10 ? 1024 : 1536);
            const int ncol = nw / 64;
            for (int v = tid; v < nw; v += 256) {
                int k = v / ncol, j = v - k * ncol;
                int xi = (j < 12) ? (64 + 12 * g + j)
                                  : ((g == 10) ? (j - 12) : (12 * g - 128 + j - 12));
                sm[SM_WT + k * 24 + j] = w_in[xi * 64 + k];
            }
            // dw1 [cpl][2][27], dw3a [cpl*2+h][27], dw3b [cpl][2][9], wout [cpl][64]
            for (int v = tid; v < 216; v += 256) {
                int cc = v / 27, t = v - cc * 27;           // cc = cpl*2 + chain/h
                int ch = 4 * g + (cc >> 1) + (cc & 1) * 64;
                sm[SM_GDW1 + v]  = w_dw1[ch * 27 + t];
                sm[SM_GDW3A + v] = w_dw3a[ch * 27 + t];
            }
            if (tid < 72) {
                int cc = tid / 9, t = tid - cc * 9;
                int ch = 4 * g + (cc >> 1) + (cc & 1) * 64;
                sm[SM_GDW3B + tid] = w_dw3b[ch * 9 + t];
            }
            {
                int cpl = tid >> 6, o = tid & 63;
                sm[SM_GWOUT + tid] = w_out[o * 64 + 4 * g + cpl];
            }
        }
        __syncthreads();   // WT/WG ready (and prev-group readers done via sync3)

        // ---- Phase A ----
        if (doA) {
            if (g < 10)       phaseA<3>(sm, g, q, m, pnA, pnB);
            else if (g == 10) phaseA<4>(sm, g, q, m, pnA, pnB);
            else              phaseA<6>(sm, g, q, m, pnA, pnB);
        }
        __syncthreads();   // XC ready

        // ---- B2: warp = (cpl, h), 180 px each ----
        {
            const int cpl = warp >> 1, h = warp & 1;
            const int cp = 4 * g + cpl;
            float wr[27];
#pragma unroll
            for (int t = 0; t < 27; ++t) wr[t] = sm[SM_GDW3A + (cpl * 2 + h) * 27 + t];
            const float bias = sm[SM_BDW3A + cp + h * 64];
            const float* xb = sm + SM_XC + (h * 12 + 3 * cpl) * 240;
            float* dst = sm + SM_D3A + cpl * 360 + h * 180;
            for (int i = lane; i < 180; i += 32) {
                int qy = i / 18, qx = i - qy * 18;
                float d = bias;
#pragma unroll
                for (int j = 0; j < 3; ++j)
#pragma unroll
                    for (int ky = 0; ky < 3; ++ky)
#pragma unroll
                        for (int kx = 0; kx < 3; ++kx)
                            d = fmaf(wr[j * 9 + ky * 3 + kx],
                                     xb[j * 240 + (qy + ky) * 20 + qx + kx], d);
                int gy = by0 + qy - 1, gx = bx0 + qx - 1;
                bool ok = ((unsigned)gy < 256u) && ((unsigned)gx < 256u);
                dst[i] = ok ? d : 0.0f;
            }
        }
        __syncthreads();   // D3A ready

        if (gh == 0) {
            // ---- B1 + proj (o 0..31) ----
#pragma unroll
            for (int cpl = 0; cpl < 4; ++cpl) {
                const int cp = 4 * g + cpl;
                float d1a = sm[SM_BDW1 + cp];
                float d1b = sm[SM_BDW1 + cp + 64];
                const float* wA = sm + SM_GDW1 + cpl * 54;
                const float* wB = wA + 27;
                const float* xcA = sm + SM_XC + (3 * cpl) * 240;
                const float* xcB = sm + SM_XC + (12 + 3 * cpl) * 240;
#pragma unroll
                for (int j = 0; j < 3; ++j)
#pragma unroll
                    for (int ky = 0; ky < 3; ++ky)
#pragma unroll
                        for (int kx = 0; kx < 3; ++kx) {
                            int xi = (tyl + 1 + ky) * 20 + (tx + 1 + kx);
                            int t = j * 9 + ky * 3 + kx;
                            d1a = fmaf(wA[t], xcA[j * 240 + xi], d1a);
                            d1b = fmaf(wB[t], xcB[j * 240 + xi], d1b);
                        }
                float g1 = gelu_exact(d1a) * d1b;
                const float4* wo = (const float4*)(sm + SM_GWOUT + cpl * 64);
#pragma unroll
                for (int mm = 0; mm < 8; ++mm) {
                    float4 w = wo[mm];
                    acc[4 * mm]     = fmaf(w.x, g1, acc[4 * mm]);
                    acc[4 * mm + 1] = fmaf(w.y, g1, acc[4 * mm + 1]);
                    acc[4 * mm + 2] = fmaf(w.z, g1, acc[4 * mm + 2]);
                    acc[4 * mm + 3] = fmaf(w.w, g1, acc[4 * mm + 3]);
                }
            }
        } else {
            // ---- B3 + proj (o 32..63) ----
#pragma unroll
            for (int cpl = 0; cpl < 4; ++cpl) {
                const int cp = 4 * g + cpl;
                float dA = sm[SM_BDW3B + cp];
                float dB = sm[SM_BDW3B + cp + 64];
                const float* wA = sm + SM_GDW3B + cpl * 18;
                const float* wB = wA + 9;
                const float* dz = sm + SM_D3A + cpl * 360;
#pragma unroll
                for (int ky = 0; ky < 3; ++ky)
#pragma unroll
                    for (int kx = 0; kx < 3; ++kx) {
                        int qi = (tyl + ky) * 18 + (tx + kx);
                        int t = ky * 3 + kx;
                        dA = fmaf(wA[t], dz[qi], dA);
                        dB = fmaf(wB[t], dz[180 + qi], dB);
                    }
                float g2 = gelu_exact(dA) * dB;
                const float4* wo = (const float4*)(sm + SM_GWOUT + cpl * 64 + 32);
#pragma unroll
                for (int mm = 0; mm < 8; ++mm) {
                    float4 w = wo[mm];
                    acc[4 * mm]     = fmaf(w.x, g2, acc[4 * mm]);
                    acc[4 * mm + 1] = fmaf(w.y, g2, acc[4 * mm + 1]);
                    acc[4 * mm + 2] = fmaf(w.z, g2, acc[4 * mm + 2]);
                    acc[4 * mm + 3] = fmaf(w.w, g2, acc[4 * mm + 3]);
                }
            }
        }
        __syncthreads();   // protect WT/WG/XC/D3A before next group's staging
    }

    // ---- write output: gh picks channel half ----
    float* ob = out + (size_t)b * 64 * 65536 + (size_t)(by0 + tyl) * 256 + (bx0 + tx);
    const int o0 = gh * 32;
#pragma unroll
    for (int i = 0; i < 32; ++i)
        ob[(size_t)(o0 + i) * 65536] = acc[i] + sm[SM_BOUT + o0 + i];
}

extern "C" void kernel_launch(void* const* d_in, const int* in_sizes, int n_in,
                              void* d_out, int out_size)
{
    (void)in_sizes; (void)n_in; (void)out_size;
    const float* x      = (const float*)d_in[0];
    const float* pneff  = (const float*)d_in[1];
    const float* w_in   = (const float*)d_in[2];
    const float* b_in   = (const float*)d_in[3];
    const float* w_pn   = (const float*)d_in[4];
    const float* b_pn   = (const float*)d_in[5];
    const float* w_dw1  = (const float*)d_in[6];
    const float* b_dw1  = (const float*)d_in[7];
    const float* w_dw3a = (const float*)d_in[8];
    const float* b_dw3a = (const float*)d_in[9];
    const float* w_dw3b = (const float*)d_in[10];
    const float* b_dw3b = (const float*)d_in[11];
    const float* w_out  = (const float*)d_in[12];
    const float* b_out  = (const float*)d_in[13];
    float* out = (float*)d_out;

    const size_t smem_bytes = SM_TOTAL * sizeof(float);
    cudaFuncSetAttribute(ffn_fused_kernel,
                         cudaFuncAttributeMaxDynamicSharedMemorySize,
                         (int)smem_bytes);
    dim3 grid(16, 32, 4);
    ffn_fused_kernel<<<grid, 256, smem_bytes>>>(
        x, pneff, w_in, b_in, w_pn, b_pn, w_dw1, b_dw1,
        w_dw3a, b_dw3a, w_dw3b, b_dw3b, w_out, b_out, out);
}